// round 3
// baseline (speedup 1.0000x reference)
#include <cuda_runtime.h>
#include <math.h>

#define N 4096
#define NN (N * N)

// Intermediate activations (no cudaMalloc allowed).
__device__ __align__(16) float g_h1[N];
__device__ __align__(16) float g_h2[N];
__device__ __align__(16) float g_s[N];

// ---------------------------------------------------------------------------
// Fused mixed-grid kernel.
//  blocks [0, gemv_rows)            : GEMV + activation (one block per row)
//  blocks [gemv_rows, gridDim.x)    : Hebbian update (1024 outputs per block)
//
// GEMV: v = W[row,:] @ x + b[row]
//   gsrc: 0 -> x_ext, 1 -> g_h1, 2 -> g_h2
//   gdst: 0 -> g_h1 = tanh(v); 1 -> g_h2 = tanh(v);
//         2 -> y_out[row] = v, g_s[row] = sigmoid(v)
//
// Hebb: new_W[o,i] = 2*A*(B*pre[i]*post[o] + C*pre[i] + D*post[o] + E)
//   H layout [o,i,m], m interleaved stride-5. Staged through smem so all
//   global loads are fully coalesced LDG.128 (avoids 5x L1tex wavefront
//   inflation of the naive strided pattern). H loads use evict-first (.cs)
//   and new_W stores are streaming so the ~1.3 GB one-touch traffic does
//   not thrash L2 for the small reusable activation vectors.
//   pre_sel: 0 -> pre_ext, 1 -> g_h1, 2 -> g_h2
//   post_sel: 1 -> g_h1, 2 -> g_h2, 3 -> g_s
// ---------------------------------------------------------------------------
__global__ void __launch_bounds__(256) fused_kernel(
    const float* __restrict__ W,
    const float* __restrict__ x_ext,
    const float* __restrict__ b,
    int gsrc, int gdst,
    float* __restrict__ y_out,
    int gemv_rows,
    const float4* __restrict__ H4,
    const float* __restrict__ pre_ext,
    int pre_sel, int post_sel,
    float4* __restrict__ outW)
{
    __shared__ float4 sm[1280];  // 20 KB; hebb staging / gemv reduction
    const int t = threadIdx.x;

    if ((int)blockIdx.x < gemv_rows) {
        // ---------------- GEMV part ----------------
        const float* x = (gsrc == 0) ? x_ext : (gsrc == 1 ? g_h1 : g_h2);
        const int row = blockIdx.x;

        const float4* Wr = reinterpret_cast<const float4*>(W) + (long long)row * (N / 4);
        const float4* xv = reinterpret_cast<const float4*>(x);

        float sum = 0.0f;
#pragma unroll
        for (int k = 0; k < 4; ++k) {
            const int idx = t + k * 256;
            float4 w  = Wr[idx];
            float4 xx = __ldg(&xv[idx]);
            sum += w.x * xx.x + w.y * xx.y;
            sum += w.z * xx.z + w.w * xx.w;
        }

#pragma unroll
        for (int off = 16; off > 0; off >>= 1)
            sum += __shfl_down_sync(0xffffffffu, sum, off);

        float* red = reinterpret_cast<float*>(sm);
        if ((t & 31) == 0) red[t >> 5] = sum;
        __syncthreads();

        if (t == 0) {
            float v = red[0];
#pragma unroll
            for (int i = 1; i < 8; ++i) v += red[i];
            v += b[row];
            if (gdst == 0) {
                g_h1[row] = tanhf(v);
            } else if (gdst == 1) {
                g_h2[row] = tanhf(v);
            } else {
                y_out[row] = v;
                g_s[row] = 1.0f / (1.0f + expf(-v));
            }
        }
    } else {
        // ---------------- Hebbian part ----------------
        const float* pre  = (pre_sel == 0) ? pre_ext : (pre_sel == 1 ? g_h1 : g_h2);
        const float* post = (post_sel == 1) ? g_h1 : (post_sel == 2 ? g_h2 : g_s);

        const int hb = blockIdx.x - gemv_rows;
        const int blockBase = hb * 1280;  // float4 index into H (< 2^25)

#pragma unroll
        for (int k = 0; k < 5; ++k)
            sm[t + 256 * k] = __ldcs(&H4[blockBase + t + 256 * k]);
        __syncthreads();

        const float4 f0 = sm[5 * t + 0];
        const float4 f1 = sm[5 * t + 1];
        const float4 f2 = sm[5 * t + 2];
        const float4 f3 = sm[5 * t + 3];
        const float4 f4 = sm[5 * t + 4];

        const int T  = hb * 256 + t;  // output float4 index
        const int e0 = T * 4;         // element index (multiple of 4, same row)

        const float  p  = post[e0 >> 12];  // o = e0 / 4096
        const float4 pr = reinterpret_cast<const float4*>(pre)[(e0 & (N - 1)) >> 2];

        // Unpack (A,B,C,D,E) per element from the 5 staged float4s.
        float4 o;
        o.x = 2.0f * f0.x * (f0.y * pr.x * p + f0.z * pr.x + f0.w * p + f1.x);
        o.y = 2.0f * f1.y * (f1.z * pr.y * p + f1.w * pr.y + f2.x * p + f2.y);
        o.z = 2.0f * f2.z * (f2.w * pr.z * p + f3.x * pr.z + f3.y * p + f3.z);
        o.w = 2.0f * f3.w * (f4.x * pr.w * p + f4.y * pr.w + f4.z * p + f4.w);

        __stcs(&outW[T], o);
    }
}

// ---------------------------------------------------------------------------
// Inputs classified by element count (robust to metadata ordering):
//   4096       -> x (first occurrence), then b0,b1,b2 in order
//   16,777,216 -> W0,W1,W2 in order
//   83,886,080 -> H0,H1,H2 in order
// Output: [y (4096) | new_W0 (NN) | new_W1 (NN) | new_W2 (NN)]
//
// Launch plan (dependencies):
//   1. gemv0                       (x -> h1)
//   2. gemv1 + hebb0 fused         (h1 -> h2  ||  needs x,h1)
//   3. gemv2 + hebb1 fused         (h2 -> y,s ||  needs h1,h2)
//   4. hebb2                       (needs h2,s)
// ---------------------------------------------------------------------------
extern "C" void kernel_launch(void* const* d_in, const int* in_sizes, int n_in,
                              void* d_out, int out_size)
{
    const float* x = nullptr;
    const float* Wp[3] = {nullptr, nullptr, nullptr};
    const float* bp[3] = {nullptr, nullptr, nullptr};
    const float* Hp[3] = {nullptr, nullptr, nullptr};
    int wi = 0, bi = 0, hi = 0;

    for (int i = 0; i < n_in; ++i) {
        const float* p = (const float*)d_in[i];
        const long long sz = (long long)in_sizes[i];
        if (sz == N) {
            if (x == nullptr) x = p;
            else if (bi < 3) bp[bi++] = p;
        } else if (sz == (long long)NN) {
            if (wi < 3) Wp[wi++] = p;
        } else if (sz == 5LL * NN) {
            if (hi < 3) Hp[hi++] = p;
        }
    }

    float* out = (float*)d_out;
    float*  y_out = out;
    float4* nW0 = (float4*)(out + N);
    float4* nW1 = (float4*)(out + N + (long long)NN);
    float4* nW2 = (float4*)(out + N + 2LL * NN);

    const int HB = NN / 4 / 256;  // 16384 hebb blocks per layer

    // 1: gemv0 only
    fused_kernel<<<N, 256>>>(Wp[0], x, bp[0], 0, 0, nullptr, N,
                             nullptr, nullptr, 0, 0, nullptr);
    // 2: gemv1 + hebb0
    fused_kernel<<<N + HB, 256>>>(Wp[1], nullptr, bp[1], 1, 1, nullptr, N,
                                  (const float4*)Hp[0], x, 0, 1, nW0);
    // 3: gemv2 + hebb1
    fused_kernel<<<N + HB, 256>>>(Wp[2], nullptr, bp[2], 2, 2, y_out, N,
                                  (const float4*)Hp[1], nullptr, 1, 2, nW1);
    // 4: hebb2 only
    fused_kernel<<<HB, 256>>>(nullptr, nullptr, nullptr, 0, 0, nullptr, 0,
                              (const float4*)Hp[2], nullptr, 2, 3, nW2);
}

// round 10
// speedup vs baseline: 1.1621x; 1.1621x over previous
#include <cuda_runtime.h>
#include <math.h>

#define N 4096
#define NN (N * N)

// Intermediate activations (no cudaMalloc allowed).
__device__ __align__(16) float g_h1[N];
__device__ __align__(16) float g_h2[N];
__device__ __align__(16) float g_s[N];

// ---------------------------------------------------------------------------
// Fused mixed-grid kernel.
//  blocks [0, gemv_rows)            : GEMV + activation (one block per row)
//  blocks [gemv_rows, gridDim.x)    : Hebbian update (1024 outputs per block)
//
// Hebb staging is an in-round A/B experiment (ncu reports per-launch dur,
// all hebb layers move identical 402MB):
//   stage_mode 0: per-warp LDG.128 staging into smem + __syncwarp
//   stage_mode 1: per-warp cp.async.bulk (TMA) gmem->smem + private mbarrier
// Mode 1 removes the 5 LDG + 5 STS per-thread L1 wavefronts (R3: L1=72.6% >
// DRAM=67% -- L1 amplification from the smem roundtrip binds first).
// pre/post loads hoisted above staging; streaming data uses .cs hints.
// ---------------------------------------------------------------------------
__global__ void __launch_bounds__(256) fused_kernel(
    const float* __restrict__ W,
    const float* __restrict__ x_ext,
    const float* __restrict__ b,
    int gsrc, int gdst,
    float* __restrict__ y_out,
    int gemv_rows,
    const float4* __restrict__ H4,
    const float* __restrict__ pre_ext,
    int pre_sel, int post_sel,
    float4* __restrict__ outW,
    int stage_mode)
{
    __shared__ float4 sm[1280];                     // 20 KB: 8 x 160-float4 slices
    __shared__ __align__(8) unsigned long long mbar8[8];  // per-warp mbarriers
    const int t = threadIdx.x;

    if ((int)blockIdx.x < gemv_rows) {
        // ---------------- GEMV part ----------------
        const float* x = (gsrc == 0) ? x_ext : (gsrc == 1 ? g_h1 : g_h2);
        const int row = blockIdx.x;

        const float4* Wr = reinterpret_cast<const float4*>(W) + (long long)row * (N / 4);
        const float4* xv = reinterpret_cast<const float4*>(x);

        float sum = 0.0f;
#pragma unroll
        for (int k = 0; k < 4; ++k) {
            const int idx = t + k * 256;
            float4 w  = __ldcs(&Wr[idx]);
            float4 xx = __ldg(&xv[idx]);
            sum += w.x * xx.x + w.y * xx.y;
            sum += w.z * xx.z + w.w * xx.w;
        }

#pragma unroll
        for (int off = 16; off > 0; off >>= 1)
            sum += __shfl_down_sync(0xffffffffu, sum, off);

        float* red = reinterpret_cast<float*>(sm);
        if ((t & 31) == 0) red[t >> 5] = sum;
        __syncthreads();

        if (t == 0) {
            float v = red[0];
#pragma unroll
            for (int i = 1; i < 8; ++i) v += red[i];
            v += b[row];
            if (gdst == 0) {
                g_h1[row] = tanhf(v);
            } else if (gdst == 1) {
                g_h2[row] = tanhf(v);
            } else {
                y_out[row] = v;
                g_s[row] = 1.0f / (1.0f + expf(-v));
            }
        }
    } else {
        // ---------------- Hebbian part (warp-autonomous) ----------------
        const float* pre  = (pre_sel == 0) ? pre_ext : (pre_sel == 1 ? g_h1 : g_h2);
        const float* post = (post_sel == 1) ? g_h1 : (post_sel == 2 ? g_h2 : g_s);

        const int hb   = blockIdx.x - gemv_rows;
        const int w    = t >> 5;
        const int lane = t & 31;

        const int warpTile = hb * 8 + w;        // 32 output float4s per warp
        const int f4base   = warpTile * 160;    // warp's H slice (float4 idx)
        float4* slice = sm + w * 160;           // 2560 B per warp

        const int T  = warpTile * 32 + lane;    // output float4 index
        const int e0 = T * 4;                   // element index (same row o)

        // Independent loads issued BEFORE staging so latency overlaps.
        const float  p  = post[e0 >> 12];       // o = e0 / 4096
        const float4 pr = reinterpret_cast<const float4*>(pre)[(e0 & (N - 1)) >> 2];

        if (stage_mode == 0) {
            // -------- Variant A: per-warp coalesced LDG.128 staging --------
#pragma unroll
            for (int k = 0; k < 5; ++k)
                slice[lane + 32 * k] = __ldcs(&H4[f4base + lane + 32 * k]);
            __syncwarp();
        } else {
            // -------- Variant B: per-warp TMA bulk copy staging --------
            const unsigned int mb  = (unsigned int)__cvta_generic_to_shared(&mbar8[w]);
            const unsigned int dst = (unsigned int)__cvta_generic_to_shared(slice);
            const void* src = (const void*)(H4 + f4base);

            if (lane == 0)
                asm volatile("mbarrier.init.shared.b64 [%0], 1;" :: "r"(mb) : "memory");
            __syncwarp();
            if (lane == 0) {
                asm volatile("mbarrier.arrive.expect_tx.shared.b64 _, [%0], %1;"
                             :: "r"(mb), "r"(2560u) : "memory");
                asm volatile(
                    "cp.async.bulk.shared::cluster.global.mbarrier::complete_tx::bytes "
                    "[%0], [%1], %2, [%3];"
                    :: "r"(dst), "l"(src), "r"(2560u), "r"(mb) : "memory");
            }
            unsigned int done = 0;
            while (!done) {
                asm volatile(
                    "{\n\t.reg .pred p;\n\t"
                    "mbarrier.try_wait.parity.acquire.cta.shared::cta.b64 p, [%1], %2;\n\t"
                    "selp.b32 %0, 1, 0, p;\n\t}"
                    : "=r"(done) : "r"(mb), "r"(0u) : "memory");
            }
        }

        const float4 f0 = slice[5 * lane + 0];
        const float4 f1 = slice[5 * lane + 1];
        const float4 f2 = slice[5 * lane + 2];
        const float4 f3 = slice[5 * lane + 3];
        const float4 f4 = slice[5 * lane + 4];

        // Unpack (A,B,C,D,E) per element from the 5 staged float4s.
        float4 o;
        o.x = 2.0f * f0.x * (f0.y * pr.x * p + f0.z * pr.x + f0.w * p + f1.x);
        o.y = 2.0f * f1.y * (f1.z * pr.y * p + f1.w * pr.y + f2.x * p + f2.y);
        o.z = 2.0f * f2.z * (f2.w * pr.z * p + f3.x * pr.z + f3.y * p + f3.z);
        o.w = 2.0f * f3.w * (f4.x * pr.w * p + f4.y * pr.w + f4.z * p + f4.w);

        __stcs(&outW[T], o);
    }
}

// ---------------------------------------------------------------------------
// Inputs classified by element count (robust to metadata ordering):
//   4096       -> x (first occurrence), then b0,b1,b2 in order
//   16,777,216 -> W0,W1,W2 in order
//   83,886,080 -> H0,H1,H2 in order
// Output: [y (4096) | new_W0 (NN) | new_W1 (NN) | new_W2 (NN)]
//
// Launch plan (dependencies + A/B assignment):
//   1. gemv0                        (x -> h1)
//   2. gemv1 + hebb0 [LDG staging]  (h1 -> h2  ||  needs x,h1)
//   3. gemv2 + hebb1 [TMA staging]  (h2 -> y,s ||  needs h1,h2)
//   4. hebb2 [LDG staging]          (needs h2,s; pure-hebb, vs R3's 71us)
// ---------------------------------------------------------------------------
extern "C" void kernel_launch(void* const* d_in, const int* in_sizes, int n_in,
                              void* d_out, int out_size)
{
    const float* x = nullptr;
    const float* Wp[3] = {nullptr, nullptr, nullptr};
    const float* bp[3] = {nullptr, nullptr, nullptr};
    const float* Hp[3] = {nullptr, nullptr, nullptr};
    int wi = 0, bi = 0, hi = 0;

    for (int i = 0; i < n_in; ++i) {
        const float* p = (const float*)d_in[i];
        const long long sz = (long long)in_sizes[i];
        if (sz == N) {
            if (x == nullptr) x = p;
            else if (bi < 3) bp[bi++] = p;
        } else if (sz == (long long)NN) {
            if (wi < 3) Wp[wi++] = p;
        } else if (sz == 5LL * NN) {
            if (hi < 3) Hp[hi++] = p;
        }
    }

    float* out = (float*)d_out;
    float*  y_out = out;
    float4* nW0 = (float4*)(out + N);
    float4* nW1 = (float4*)(out + N + (long long)NN);
    float4* nW2 = (float4*)(out + N + 2LL * NN);

    const int HB = NN / 4 / 256;  // 16384 hebb blocks per layer

    // 1: gemv0 only
    fused_kernel<<<N, 256>>>(Wp[0], x, bp[0], 0, 0, nullptr, N,
                             nullptr, nullptr, 0, 0, nullptr, 0);
    // 2: gemv1 + hebb0  [variant A: LDG staging]
    fused_kernel<<<N + HB, 256>>>(Wp[1], nullptr, bp[1], 1, 1, nullptr, N,
                                  (const float4*)Hp[0], x, 0, 1, nW0, 0);
    // 3: gemv2 + hebb1  [variant B: TMA staging]
    fused_kernel<<<N + HB, 256>>>(Wp[2], nullptr, bp[2], 2, 2, y_out, N,
                                  (const float4*)Hp[1], nullptr, 1, 2, nW1, 1);
    // 4: hebb2 only     [variant A: LDG staging, pure-hebb baseline compare]
    fused_kernel<<<HB, 256>>>(nullptr, nullptr, nullptr, 0, 0, nullptr, 0,
                              (const float4*)Hp[2], nullptr, 2, 3, nW2, 0);
}